// round 3
// baseline (speedup 1.0000x reference)
#include <cuda_runtime.h>
#include <cuda_bf16.h>
#include <math.h>

#define NG   1024
#define IMG  256
#define TILE 16
#define NTIL (IMG / TILE)          // 16 tiles per dim
#define HW   (IMG * IMG)           // 65536

// Preprocessed gaussian data (device scratch; no allocations).
// g_p0 = {cx, cy, ka, kb}   (ka,kb,kc already scaled by -0.5*log2(e) appropriately)
// g_p1 = {kc, fr, fg, fb}
// g_r2 = cull radius^2 (pixel^2)
__device__ float4 g_p0[NG];
__device__ float4 g_p1[NG];
__device__ float  g_r2[NG];

__global__ void prep_kernel(const float* __restrict__ xyz,
                            const float* __restrict__ chol,
                            const float* __restrict__ opac,
                            const float* __restrict__ feat)
{
    int i = blockIdx.x * blockDim.x + threadIdx.x;
    if (i >= NG) return;

    float mx = tanhf(xyz[2 * i + 0]);
    float my = tanhf(xyz[2 * i + 1]);
    float cx = 0.5f * (float)IMG * (mx + 1.0f);
    float cy = 0.5f * (float)IMG * (my + 1.0f);

    float l1 = chol[3 * i + 0] + 0.5f;
    float l2 = chol[3 * i + 1] + 0.0f;
    float l3 = chol[3 * i + 2] + 0.5f;

    float a = l1 * l1;
    float b = l1 * l2;
    float c = l2 * l2 + l3 * l3;
    float det = a * c - b * b;          // == (l1*l3)^2 >= 0.0625
    float inv = 1.0f / det;
    float conic_a =  c * inv;
    float conic_b = -b * inv;
    float conic_c =  a * inv;

    // sigma = 0.5*ca*dx^2 + 0.5*cc*dy^2 + cb*dx*dy ; w = exp(-sigma) = exp2(t)
    // with t = ka*dx^2 + kb*dx*dy + kc*dy^2 (negative-definite constants):
    const float L2E = 1.4426950408889634f;
    float ka = -0.5f * conic_a * L2E;
    float kb = -conic_b * L2E;
    float kc = -0.5f * conic_c * L2E;

    // Cull radius: |t| >= lam_min * r^2 for the PD form -t.
    // lam_min of [[-ka, -kb/2],[-kb/2, -kc]]
    float pa = -ka, pc = -kc, pb2 = -0.5f * kb;
    float tr2 = 0.5f * (pa + pc);
    float dd  = 0.5f * (pa - pc);
    float lam_min = tr2 - sqrtf(dd * dd + pb2 * pb2);
    const float T2 = 36.1f;             // 25 nats in log2 units
    float r2 = T2 / fmaxf(lam_min, 1e-12f);

    float o = opac[i];
    g_p0[i] = make_float4(cx, cy, ka, kb);
    g_p1[i] = make_float4(kc, feat[3 * i + 0] * o,
                              feat[3 * i + 1] * o,
                              feat[3 * i + 2] * o);
    g_r2[i] = r2;
}

__global__ __launch_bounds__(256, 4)
void render_kernel(float* __restrict__ out)
{
    __shared__ float4 s0[NG];
    __shared__ float4 s1[NG];
    __shared__ int    s_warpcnt[8];
    __shared__ int    s_total;

    const int tid  = threadIdx.x;
    const int warp = tid >> 5;
    const int lane = tid & 31;

    const float x0 = (float)(blockIdx.x * TILE);
    const float y0 = (float)(blockIdx.y * TILE);
    const float xlo = x0 + 0.5f, xhi = x0 + (float)TILE - 0.5f;
    const float ylo = y0 + 0.5f, yhi = y0 + (float)TILE - 0.5f;

    if (tid == 0) s_total = 0;
    __syncthreads();

    // Deterministic (order-preserving) compaction of intersecting gaussians.
    #pragma unroll
    for (int base = 0; base < NG; base += 256) {
        int g = base + tid;
        float4 p0 = g_p0[g];
        float  r2 = g_r2[g];
        float dxc = p0.x - fminf(fmaxf(p0.x, xlo), xhi);
        float dyc = p0.y - fminf(fmaxf(p0.y, ylo), yhi);
        bool hit = (dxc * dxc + dyc * dyc) <= r2;

        unsigned m = __ballot_sync(0xffffffffu, hit);
        if (lane == 0) s_warpcnt[warp] = __popc(m);
        __syncthreads();                       // warpcnt visible; s_total stable

        int offset = s_total;
        #pragma unroll
        for (int w = 0; w < 8; w++)
            if (w < warp) offset += s_warpcnt[w];
        offset += __popc(m & ((1u << lane) - 1u));

        if (hit) {
            s0[offset] = p0;
            s1[offset] = g_p1[g];
        }
        __syncthreads();                       // all reads of s_total done
        if (tid == 0) {
            int t = 0;
            #pragma unroll
            for (int w = 0; w < 8; w++) t += s_warpcnt[w];
            s_total += t;
        }
        __syncthreads();                       // updated total visible
    }

    const int count = s_total;

    // One pixel per thread.
    const int   pxi = blockIdx.x * TILE + (tid & (TILE - 1));
    const int   pyi = blockIdx.y * TILE + (tid >> 4);
    const float px  = (float)pxi + 0.5f;
    const float py  = (float)pyi + 0.5f;

    float accr = 0.0f, accg = 0.0f, accb = 0.0f;
    for (int i = 0; i < count; i++) {
        float4 p0 = s0[i];                     // broadcast reads
        float4 p1 = s1[i];
        float dx = px - p0.x;
        float dy = py - p0.y;
        // t = ka*dx^2 + kb*dx*dy + kc*dy^2   (<= 0)
        float t = fmaf(p0.z * dx, dx, fmaf(p1.x * dy, dy, (p0.w * dx) * dy));
        float w = exp2f(t);
        accr = fmaf(w, p1.y, accr);
        accg = fmaf(w, p1.z, accg);
        accb = fmaf(w, p1.w, accb);
    }

    accr = fminf(fmaxf(accr, 0.0f), 1.0f);
    accg = fminf(fmaxf(accg, 0.0f), 1.0f);
    accb = fminf(fmaxf(accb, 0.0f), 1.0f);

    const int p = pyi * IMG + pxi;
    out[0 * HW + p] = accr;
    out[1 * HW + p] = accg;
    out[2 * HW + p] = accb;
}

extern "C" void kernel_launch(void* const* d_in, const int* in_sizes, int n_in,
                              void* d_out, int out_size)
{
    const float* xyz  = (const float*)d_in[0];   // (N,2)
    const float* chol = (const float*)d_in[1];   // (N,3)
    const float* opac = (const float*)d_in[2];   // (N,1)
    const float* feat = (const float*)d_in[3];   // (N,3)
    float* out = (float*)d_out;                  // (1,3,256,256)

    prep_kernel<<<NG / 256, 256>>>(xyz, chol, opac, feat);
    dim3 grid(NTIL, NTIL);
    render_kernel<<<grid, 256>>>(out);
}

// round 4
// speedup vs baseline: 1.2620x; 1.2620x over previous
#include <cuda_runtime.h>
#include <cuda_bf16.h>
#include <math.h>

#define NG   1024
#define IMG  256
#define TILE 16
#define NTIL (IMG / TILE)          // 16
#define HW   (IMG * IMG)           // 65536
#define GPT  4                     // gaussians per thread (256 thr * 4 = 1024)

// Single fused kernel: every block re-derives all gaussian params from the raw
// inputs (cheap: fma/MUFU pipes are idle), culls against its 16x16 tile with a
// single-pass order-preserving compaction (2 barriers), then splats.
__global__ __launch_bounds__(256)
void fused_render_kernel(const float* __restrict__ xyz,
                         const float* __restrict__ chol,
                         const float* __restrict__ opac,
                         const float* __restrict__ feat,
                         float* __restrict__ out)
{
    __shared__ float4 s0[NG];      // {cx, cy, ka, kb}
    __shared__ float4 s1[NG];      // {kc, fr, fg, fb}
    __shared__ int    s_warpcnt[8];

    const int tid  = threadIdx.x;
    const int warp = tid >> 5;
    const int lane = tid & 31;

    const float x0  = (float)(blockIdx.x * TILE);
    const float y0  = (float)(blockIdx.y * TILE);
    const float xlo = x0 + 0.5f, xhi = x0 + (float)TILE - 0.5f;
    const float ylo = y0 + 0.5f, yhi = y0 + (float)TILE - 0.5f;

    // ---- batched contiguous loads: thread t owns gaussians 4t..4t+3 ----
    const float4* xyz4 = (const float4*)xyz;   // 8 floats  = 2 x float4
    const float4* ch4  = (const float4*)chol;  // 12 floats = 3 x float4
    const float4* op4  = (const float4*)opac;  // 4 floats  = 1 x float4
    const float4* ft4  = (const float4*)feat;  // 12 floats = 3 x float4

    float4 xyA = xyz4[tid * 2 + 0];
    float4 xyB = xyz4[tid * 2 + 1];
    float4 chA = ch4[tid * 3 + 0];
    float4 chB = ch4[tid * 3 + 1];
    float4 chC = ch4[tid * 3 + 2];
    float4 opV = op4[tid];
    float4 ftA = ft4[tid * 3 + 0];
    float4 ftB = ft4[tid * 3 + 1];
    float4 ftC = ft4[tid * 3 + 2];

    float xyv[8]  = {xyA.x, xyA.y, xyA.z, xyA.w, xyB.x, xyB.y, xyB.z, xyB.w};
    float chv[12] = {chA.x, chA.y, chA.z, chA.w, chB.x, chB.y, chB.z, chB.w,
                     chC.x, chC.y, chC.z, chC.w};
    float ftv[12] = {ftA.x, ftA.y, ftA.z, ftA.w, ftB.x, ftB.y, ftB.z, ftB.w,
                     ftC.x, ftC.y, ftC.z, ftC.w};
    float opv[4]  = {opV.x, opV.y, opV.z, opV.w};

    // ---- per-gaussian prep + tile cull ----
    const float L2E = 1.4426950408889634f;
    float4 p0v[GPT], p1v[GPT];
    bool   hitv[GPT];
    int    c = 0;

    #pragma unroll
    for (int j = 0; j < GPT; j++) {
        float mx = tanhf(xyv[2 * j + 0]);
        float my = tanhf(xyv[2 * j + 1]);
        float cx = 0.5f * (float)IMG * (mx + 1.0f);
        float cy = 0.5f * (float)IMG * (my + 1.0f);

        float l1 = chv[3 * j + 0] + 0.5f;
        float l2 = chv[3 * j + 1];
        float l3 = chv[3 * j + 2] + 0.5f;

        float a = l1 * l1;
        float b = l1 * l2;
        float cc = l2 * l2 + l3 * l3;
        float inv = 1.0f / (a * cc - b * b);   // det = (l1*l3)^2 >= 0.0625

        // w = exp2(ka*dx^2 + kb*dx*dy + kc*dy^2), neg.-definite quad form
        float ka = -0.5f * (cc * inv) * L2E;
        float kb =  (b * inv) * L2E;
        float kc = -0.5f * (a * inv) * L2E;

        // cull radius^2 from smallest eigenvalue of the PD form
        float pa = -ka, pc = -kc, pb2 = -0.5f * kb;
        float tr2 = 0.5f * (pa + pc);
        float dd  = 0.5f * (pa - pc);
        float lam_min = tr2 - sqrtf(dd * dd + pb2 * pb2);
        float r2 = 36.1f / fmaxf(lam_min, 1e-12f);   // 25 nats in log2 units

        float o = opv[j];
        p0v[j] = make_float4(cx, cy, ka, kb);
        p1v[j] = make_float4(kc, ftv[3 * j + 0] * o,
                                 ftv[3 * j + 1] * o,
                                 ftv[3 * j + 2] * o);

        float dxc = cx - fminf(fmaxf(cx, xlo), xhi);
        float dyc = cy - fminf(fmaxf(cy, ylo), yhi);
        bool hit = (dxc * dxc + dyc * dyc) <= r2;
        hitv[j] = hit;
        c += hit ? 1 : 0;
    }

    // ---- single-pass order-preserving compaction (2 barriers) ----
    int inc = c;
    #pragma unroll
    for (int d = 1; d < 32; d <<= 1) {
        int v = __shfl_up_sync(0xffffffffu, inc, d);
        if (lane >= d) inc += v;
    }
    if (lane == 31) s_warpcnt[warp] = inc;
    __syncthreads();

    int off = inc - c;
    int count = 0;
    #pragma unroll
    for (int w = 0; w < 8; w++) {
        int wc = s_warpcnt[w];
        if (w < warp) off += wc;
        count += wc;
    }

    #pragma unroll
    for (int j = 0; j < GPT; j++) {
        if (hitv[j]) {
            s0[off] = p0v[j];
            s1[off] = p1v[j];
            off++;
        }
    }
    __syncthreads();

    // ---- splat: one pixel per thread ----
    const int   pxi = blockIdx.x * TILE + (tid & (TILE - 1));
    const int   pyi = blockIdx.y * TILE + (tid >> 4);
    const float px  = (float)pxi + 0.5f;
    const float py  = (float)pyi + 0.5f;

    float accr = 0.0f, accg = 0.0f, accb = 0.0f;
    #pragma unroll 2
    for (int i = 0; i < count; i++) {
        float4 p0 = s0[i];                 // broadcast smem reads
        float4 p1 = s1[i];
        float dx = px - p0.x;
        float dy = py - p0.y;
        float t = fmaf(p0.z * dx, dx, fmaf(p1.x * dy, dy, (p0.w * dx) * dy));
        float w = exp2f(t);
        accr = fmaf(w, p1.y, accr);
        accg = fmaf(w, p1.z, accg);
        accb = fmaf(w, p1.w, accb);
    }

    accr = fminf(fmaxf(accr, 0.0f), 1.0f);
    accg = fminf(fmaxf(accg, 0.0f), 1.0f);
    accb = fminf(fmaxf(accb, 0.0f), 1.0f);

    const int p = pyi * IMG + pxi;
    out[0 * HW + p] = accr;
    out[1 * HW + p] = accg;
    out[2 * HW + p] = accb;
}

extern "C" void kernel_launch(void* const* d_in, const int* in_sizes, int n_in,
                              void* d_out, int out_size)
{
    const float* xyz  = (const float*)d_in[0];   // (N,2)
    const float* chol = (const float*)d_in[1];   // (N,3)
    const float* opac = (const float*)d_in[2];   // (N,1)
    const float* feat = (const float*)d_in[3];   // (N,3)
    float* out = (float*)d_out;                  // (1,3,256,256)

    dim3 grid(NTIL, NTIL);
    fused_render_kernel<<<grid, 256>>>(xyz, chol, opac, feat, out);
}